// round 9
// baseline (speedup 1.0000x reference)
#include <cuda_runtime.h>
#include <math.h>

// Problem shape (fixed by the dataset): [B=32, C=1, H=512, W=512] fp32.
#define BATCH 32
#define HH 512
#define WW 512
#define W4 (WW / 4)       // 128 float4 per row
#define KER 31
#define PAD 15
#define NPIX (HH * WW)
#define ROWS 16           // output rows per block
#define KB 4              // rows per barrier batch (ping-pong)
#define TILES (HH / ROWS) // 32
#define NBLOCKS (TILES * BATCH)  // 1024

// Per-(batch,tile) partials: x=sum(weit), y=sum(weit*bce), z=inter, w=union
__device__ float4 g_part[BATCH][TILES];
__device__ int g_count = 0;   // last-block detector; self-resets each launch

__inline__ __device__ float warp_reduce(float v) {
    #pragma unroll
    for (int o = 16; o > 0; o >>= 1) v += __shfl_down_sync(0xffffffffu, v, o);
    return v;
}

// Padded per-row buffers: float4 index 4+tid holds thread tid's vsum (cols
// 4t..4t+3); indices 0..3 and 132..135 are zero pads. G[i] = sum4(P[i]).
__global__ void __launch_bounds__(128, 8)
structure_loss_kernel(const float* __restrict__ x,
                      const float* __restrict__ t,
                      float* __restrict__ out) {
    __shared__ float4 Pb[2][KB][136];
    __shared__ float  Gb[2][KB][136];
    __shared__ float red4[4][4];
    __shared__ float sl[BATCH];
    __shared__ int s_last;

    const int tid  = threadIdx.x;   // 0..127, owns cols 4*tid..4*tid+3
    const int tile = blockIdx.x;    // 0..31
    const int b    = blockIdx.y;    // 0..31
    const int h0   = tile * ROWS;

    // zero the pads of both buffers, all KB rows (read-only thereafter)
    if (tid < 4) {
        const float4 z4 = make_float4(0.f, 0.f, 0.f, 0.f);
        #pragma unroll
        for (int u = 0; u < 2; ++u)
            #pragma unroll
            for (int r = 0; r < KB; ++r) {
                Pb[u][r][tid] = z4;        Pb[u][r][132 + tid] = z4;
                Gb[u][r][tid] = 0.f;       Gb[u][r][132 + tid] = 0.f;
            }
    }

    const float4* tc = (const float4*)(t + (size_t)b * NPIX) + tid;

    // ---- initial vertical window for row h0: rows [h0-15, h0+15] clipped ----
    float4 s = make_float4(0.f, 0.f, 0.f, 0.f);
    {
        const int lo = (h0 - PAD < 0) ? 0 : h0 - PAD;
        const int hi = (h0 + PAD > HH - 1) ? HH - 1 : h0 + PAD;
        #pragma unroll 8
        for (int r = lo; r <= hi; ++r) {
            float4 q = tc[(size_t)r * W4];
            s.x += q.x; s.y += q.y; s.z += q.z; s.w += q.w;
        }
    }

    float a0 = 0.f, a1 = 0.f, a2 = 0.f, a3 = 0.f;
    const float inv = 1.0f / (float)(KER * KER);

    for (int jb = 0; jb < ROWS / KB; ++jb) {
        const int buf = jb & 1;

        // ---- publish KB vsum rows (slide between rows), then one barrier ----
        #pragma unroll
        for (int r = 0; r < KB; ++r) {
            const int j = jb * KB + r;
            if (j > 0) {
                const int add = h0 + j + PAD;
                const int sub = h0 + j - PAD - 1;
                if (add < HH) {
                    float4 q = tc[(size_t)add * W4];
                    s.x += q.x; s.y += q.y; s.z += q.z; s.w += q.w;
                }
                if (sub >= 0) {
                    float4 q = tc[(size_t)sub * W4];
                    s.x -= q.x; s.y -= q.y; s.z -= q.z; s.w -= q.w;
                }
            }
            Pb[buf][r][4 + tid] = s;
            Gb[buf][r][4 + tid] = (s.x + s.y) + (s.z + s.w);
        }
        __syncthreads();

        // ---- compute KB rows back-to-back (no barriers) ----
        #pragma unroll
        for (int r = 0; r < KB; ++r) {
            const float4* P = Pb[buf][r];
            const float*  G = Gb[buf][r];

            const size_t rowoff =
                ((size_t)b * HH + h0 + jb * KB + r) * (size_t)WW + 4 * tid;
            const float4 t4 = *(const float4*)(t + rowoff);
            const float4 x4 = *(const float4*)(x + rowoff);

            const float4 sm = P[tid];      // cols 4t-16 .. 4t-13
            const float4 sp = P[tid + 8];  // cols 4t+16 .. 4t+19
            float S0 = G[tid] - sm.x;
            #pragma unroll
            for (int i = 1; i < 8; ++i) S0 += G[tid + i];
            const float S1 = S0 - sm.y + sp.x;
            const float S2 = S1 - sm.z + sp.y;
            const float S3 = S2 - sm.w + sp.z;
            const float S[4]   = {S0, S1, S2, S3};
            const float tt_[4] = {t4.x, t4.y, t4.z, t4.w};
            const float xx_[4] = {x4.x, x4.y, x4.z, x4.w};

            #pragma unroll
            for (int k = 0; k < 4; ++k) {
                const float tt = tt_[k];
                const float xx = xx_[k];
                const float weit = 1.0f + 5.0f * fabsf(S[k] * inv - tt);
                const float e    = __expf(-fabsf(xx));                 // e^{-|x|}
                const float bce  = fmaxf(xx, 0.0f) - xx * tt + __logf(1.0f + e);
                const float p    = __fdividef((xx >= 0.0f ? 1.0f : e), 1.0f + e);
                a0 += weit;
                a1 += weit * bce;
                a2 += p * tt * weit;
                a3 += (p + tt) * weit;
            }
        }
    }

    // ---- block reduce -> one float4 per block ----
    a0 = warp_reduce(a0);
    a1 = warp_reduce(a1);
    a2 = warp_reduce(a2);
    a3 = warp_reduce(a3);
    const int warp = tid >> 5;
    const int lane = tid & 31;
    if (lane == 0) {
        red4[warp][0] = a0; red4[warp][1] = a1;
        red4[warp][2] = a2; red4[warp][3] = a3;
    }
    __syncthreads();

    if (tid == 0) {
        float4 r;
        r.x = (red4[0][0] + red4[1][0]) + (red4[2][0] + red4[3][0]);
        r.y = (red4[0][1] + red4[1][1]) + (red4[2][1] + red4[3][1]);
        r.z = (red4[0][2] + red4[1][2]) + (red4[2][2] + red4[3][2]);
        r.w = (red4[0][3] + red4[1][3]) + (red4[2][3] + red4[3][3]);
        g_part[b][tile] = r;
        __threadfence();
        int prev = atomicAdd(&g_count, 1);
        s_last = (prev == NBLOCKS - 1) ? 1 : 0;
        if (s_last) atomicExch(&g_count, 0);   // reset for next graph replay
    }
    __syncthreads();
    if (!s_last) return;

    // ---- last block: final reduction (fixed order => deterministic) ----
    __threadfence();  // acquire: see all g_part writes
    {
        // thread i: batch bb = i>>2, quarter p = i&3 -> tiles p*8 .. p*8+7
        const int bb = tid >> 2;
        const int p  = tid & 3;
        float c0 = 0.f, c1 = 0.f, c2 = 0.f, c3 = 0.f;
        #pragma unroll
        for (int k = 0; k < 8; ++k) {
            float4 q = g_part[bb][p * 8 + k];
            c0 += q.x; c1 += q.y; c2 += q.z; c3 += q.w;
        }
        #pragma unroll
        for (int o = 1; o <= 2; o <<= 1) {
            c0 += __shfl_xor_sync(0xffffffffu, c0, o);
            c1 += __shfl_xor_sync(0xffffffffu, c1, o);
            c2 += __shfl_xor_sync(0xffffffffu, c2, o);
            c3 += __shfl_xor_sync(0xffffffffu, c3, o);
        }
        if (p == 0) {
            const float wbce = c1 / c0;
            const float wiou = 1.0f - (c2 + 1.0f) / ((c3 - c2) + 1.0f);
            sl[bb] = wbce + wiou;
        }
    }
    __syncthreads();
    if (tid < 32) {
        float l = sl[tid];
        l = warp_reduce(l);
        if (tid == 0) out[0] = l * (1.0f / (float)BATCH);
    }
}

// ---------------------------------------------------------------------------
extern "C" void kernel_launch(void* const* d_in, const int* in_sizes, int n_in,
                              void* d_out, int out_size) {
    const float* x = (const float*)d_in[0];  // input (logits)
    const float* t = (const float*)d_in[1];  // target
    float* out = (float*)d_out;

    dim3 grid(TILES, BATCH);
    structure_loss_kernel<<<grid, 128>>>(x, t, out);
}